// round 1
// baseline (speedup 1.0000x reference)
#include <cuda_runtime.h>
#include <cuda_bf16.h>
#include <cstdint>

// ---------------------------------------------------------------------------
// RelKDAdapter: src_proj = x_src @ W_src  (fp32 SGEMM, M=100000 K=256 N=128)
//               deg      = max(count of edges per dst, 1)
//               dst      = segment_mean of src_proj[edge_col] over edge_row
// Strategy: CSR build (int atomics + scan) then warp-per-row gather/sum.
// Avoids 82M float atomics entirely.
// ---------------------------------------------------------------------------

#define DD_SRC   256
#define DD_DST   64
#define DD_REL   128
#define MAX_NDST 100000
#define MAX_E    640000
#define SCAN_B   1024
#define MAX_SCAN_BLOCKS 128   // ceil(100000/1024)=98

__device__ int g_deg[MAX_NDST];
__device__ int g_rowptr[MAX_NDST + 1];
__device__ int g_cursor[MAX_NDST];
__device__ int g_cols[MAX_E];
__device__ int g_blksums[MAX_SCAN_BLOCKS];

// ---------------------------------------------------------------------------
// K0: zero degree counters
// ---------------------------------------------------------------------------
__global__ void k_zero_deg(int n) {
    int i = blockIdx.x * blockDim.x + threadIdx.x;
    if (i < n) g_deg[i] = 0;
}

// ---------------------------------------------------------------------------
// K1: count degrees (int atomics, cheap)
// ---------------------------------------------------------------------------
__global__ void k_count(const int* __restrict__ erow, int E) {
    int e = blockIdx.x * blockDim.x + threadIdx.x;
    if (e < E) atomicAdd(&g_deg[erow[e]], 1);
}

// ---------------------------------------------------------------------------
// K2: per-block exclusive scan (Hillis-Steele inclusive, then subtract self)
// ---------------------------------------------------------------------------
__global__ void k_scan_partial(int n) {
    __shared__ int sh[SCAN_B];
    int i = blockIdx.x * SCAN_B + threadIdx.x;
    int v = (i < n) ? g_deg[i] : 0;
    sh[threadIdx.x] = v;
    __syncthreads();
#pragma unroll
    for (int off = 1; off < SCAN_B; off <<= 1) {
        int t = (threadIdx.x >= off) ? sh[threadIdx.x - off] : 0;
        __syncthreads();
        sh[threadIdx.x] += t;
        __syncthreads();
    }
    if (i < n) g_rowptr[i] = sh[threadIdx.x] - v;  // exclusive within block
    if (threadIdx.x == SCAN_B - 1) g_blksums[blockIdx.x] = sh[SCAN_B - 1];
}

// ---------------------------------------------------------------------------
// K3: serial scan of block sums (98 values — negligible)
// ---------------------------------------------------------------------------
__global__ void k_scan_sums(int nb) {
    if (blockIdx.x == 0 && threadIdx.x == 0) {
        int run = 0;
        for (int b = 0; b < nb; b++) {
            int t = g_blksums[b];
            g_blksums[b] = run;
            run += t;
        }
    }
}

// ---------------------------------------------------------------------------
// K4: add block offsets, init cursors, cap rowptr
// ---------------------------------------------------------------------------
__global__ void k_scan_add(int n, int E) {
    int i = blockIdx.x * SCAN_B + threadIdx.x;
    if (i < n) {
        int v = g_rowptr[i] + g_blksums[blockIdx.x];
        g_rowptr[i] = v;
        g_cursor[i] = v;
    }
    if (i == 0) g_rowptr[n] = E;
}

// ---------------------------------------------------------------------------
// K5: scatter edge cols into CSR buckets
// ---------------------------------------------------------------------------
__global__ void k_fill(const int* __restrict__ erow, const int* __restrict__ ecol, int E) {
    int e = blockIdx.x * blockDim.x + threadIdx.x;
    if (e < E) {
        int r = erow[e];
        int p = atomicAdd(&g_cursor[r], 1);
        g_cols[p] = ecol[e];
    }
}

// ---------------------------------------------------------------------------
// K6: SGEMM  C[M,128] = A[M,256] @ B[256,128]
// BM=128 BN=128 BK=16, 256 threads, 8x8 microtile per thread
// ---------------------------------------------------------------------------
#define GM_BM 128
#define GM_BN 128
#define GM_BK 16

__global__ __launch_bounds__(256, 2)
void k_gemm(const float* __restrict__ A, const float* __restrict__ B,
            float* __restrict__ C, int M) {
    __shared__ float As[GM_BK][GM_BM];       // transposed A tile
    __shared__ float Bs[GM_BK][GM_BN];

    const int tid = threadIdx.x;
    const int tx = tid & 15;       // 0..15 -> N
    const int ty = tid >> 4;       // 0..15 -> M
    const int block_row = blockIdx.x * GM_BM;

    float acc[8][8];
#pragma unroll
    for (int i = 0; i < 8; i++)
#pragma unroll
        for (int j = 0; j < 8; j++) acc[i][j] = 0.f;

    for (int k0 = 0; k0 < DD_SRC; k0 += GM_BK) {
        // Load A tile: 128 rows x 16 cols = 512 float4
#pragma unroll
        for (int it = 0; it < 2; it++) {
            int idx = tid + it * 256;      // 0..511
            int r   = idx >> 2;            // 0..127
            int cq  = idx & 3;             // float4 index within 16
            int grow = block_row + r;
            float4 v = make_float4(0.f, 0.f, 0.f, 0.f);
            if (grow < M)
                v = *(const float4*)(A + (size_t)grow * DD_SRC + k0 + cq * 4);
            As[cq * 4 + 0][r] = v.x;
            As[cq * 4 + 1][r] = v.y;
            As[cq * 4 + 2][r] = v.z;
            As[cq * 4 + 3][r] = v.w;
        }
        // Load B tile: 16 rows x 128 cols = 512 float4
#pragma unroll
        for (int it = 0; it < 2; it++) {
            int idx = tid + it * 256;
            int r   = idx >> 5;            // 0..15
            int c4  = idx & 31;            // float4 col
            float4 v = *(const float4*)(B + (size_t)(k0 + r) * DD_REL + c4 * 4);
            *(float4*)&Bs[r][c4 * 4] = v;
        }
        __syncthreads();

#pragma unroll
        for (int k = 0; k < GM_BK; k++) {
            float a[8], b[8];
            *(float4*)&a[0] = *(const float4*)&As[k][ty * 8];
            *(float4*)&a[4] = *(const float4*)&As[k][ty * 8 + 4];
            *(float4*)&b[0] = *(const float4*)&Bs[k][tx * 8];
            *(float4*)&b[4] = *(const float4*)&Bs[k][tx * 8 + 4];
#pragma unroll
            for (int i = 0; i < 8; i++)
#pragma unroll
                for (int j = 0; j < 8; j++)
                    acc[i][j] = fmaf(a[i], b[j], acc[i][j]);
        }
        __syncthreads();
    }

    // Store 8x8 per thread
#pragma unroll
    for (int i = 0; i < 8; i++) {
        int grow = block_row + ty * 8 + i;
        if (grow < M) {
            float* cp = C + (size_t)grow * DD_REL + tx * 8;
            *(float4*)(cp)     = make_float4(acc[i][0], acc[i][1], acc[i][2], acc[i][3]);
            *(float4*)(cp + 4) = make_float4(acc[i][4], acc[i][5], acc[i][6], acc[i][7]);
        }
    }
}

// ---------------------------------------------------------------------------
// K7: aggregation — one warp per dst row, float4 per lane (32*16B = 512B row)
// ---------------------------------------------------------------------------
__global__ void k_aggregate(const float* __restrict__ src_proj,
                            float* __restrict__ dst_out,
                            float* __restrict__ deg_out,
                            int n_dst) {
    int gwarp = (blockIdx.x * blockDim.x + threadIdx.x) >> 5;
    int lane  = threadIdx.x & 31;
    if (gwarp >= n_dst) return;

    int beg = g_rowptr[gwarp];
    int end = g_rowptr[gwarp + 1];

    const float4* sp = (const float4*)src_proj;   // row stride = 32 float4
    float4 acc = make_float4(0.f, 0.f, 0.f, 0.f);

    int e = beg;
    // 2-way unroll for MLP
    for (; e + 2 <= end; e += 2) {
        int c0 = g_cols[e];
        int c1 = g_cols[e + 1];
        float4 v0 = __ldg(&sp[(size_t)c0 * 32 + lane]);
        float4 v1 = __ldg(&sp[(size_t)c1 * 32 + lane]);
        acc.x += v0.x + v1.x;
        acc.y += v0.y + v1.y;
        acc.z += v0.z + v1.z;
        acc.w += v0.w + v1.w;
    }
    if (e < end) {
        int c0 = g_cols[e];
        float4 v0 = __ldg(&sp[(size_t)c0 * 32 + lane]);
        acc.x += v0.x; acc.y += v0.y; acc.z += v0.z; acc.w += v0.w;
    }

    float d = fmaxf((float)(end - beg), 1.f);
    float inv = 1.f / d;
    acc.x *= inv; acc.y *= inv; acc.z *= inv; acc.w *= inv;

    ((float4*)dst_out)[(size_t)gwarp * 32 + lane] = acc;
    if (lane == 0) deg_out[gwarp] = d;
}

// ---------------------------------------------------------------------------
// launch
// ---------------------------------------------------------------------------
extern "C" void kernel_launch(void* const* d_in, const int* in_sizes, int n_in,
                              void* d_out, int out_size) {
    const float* x_src = (const float*)d_in[0];
    // d_in[1] = x_dst (unused), d_in[3] = W_dst (unused — dst_proj is deleted)
    const float* W_src = (const float*)d_in[2];
    const int*   erow  = (const int*)d_in[4];
    const int*   ecol  = (const int*)d_in[5];

    const int N_src = in_sizes[0] / DD_SRC;
    const int N_dst = in_sizes[1] / DD_DST;
    const int E     = in_sizes[4];

    float* out         = (float*)d_out;
    float* dst_out     = out;                                    // [N_dst,128]
    float* srcproj_out = out + (size_t)N_dst * DD_REL;           // [N_src,128]
    float* deg_out     = srcproj_out + (size_t)N_src * DD_REL;   // [N_dst]

    // --- CSR build ---
    k_zero_deg<<<(N_dst + 255) / 256, 256>>>(N_dst);
    k_count<<<(E + 255) / 256, 256>>>(erow, E);

    int nb = (N_dst + SCAN_B - 1) / SCAN_B;
    k_scan_partial<<<nb, SCAN_B>>>(N_dst);
    k_scan_sums<<<1, 32>>>(nb);
    k_scan_add<<<nb, SCAN_B>>>(N_dst, E);
    k_fill<<<(E + 255) / 256, 256>>>(erow, ecol, E);

    // --- projection GEMM (writes src_proj output region) ---
    int gm_blocks = (N_src + GM_BM - 1) / GM_BM;
    k_gemm<<<gm_blocks, 256>>>(x_src, W_src, srcproj_out, N_src);

    // --- aggregation (reads src_proj from d_out) ---
    int warps_per_block = 256 / 32;
    int agg_blocks = (N_dst + warps_per_block - 1) / warps_per_block;
    k_aggregate<<<agg_blocks, 256>>>(srcproj_out, dst_out, deg_out, N_dst);
}

// round 2
// speedup vs baseline: 1.8606x; 1.8606x over previous
#include <cuda_runtime.h>
#include <cuda_bf16.h>
#include <cstdint>

// ---------------------------------------------------------------------------
// RelKDAdapter on GB300:
//   src_proj = x_src @ W_src   (tf32 tensor-core GEMM, M=100000 K=256 N=128)
//   deg      = max(#edges per dst, 1)
//   dst      = segment-mean of src_proj[edge_col] over edge_row  (CSR gather)
// ---------------------------------------------------------------------------

#define DD_SRC   256
#define DD_DST   64
#define DD_REL   128
#define MAX_NDST 100000
#define MAX_E    640000
#define SCAN_B   1024
#define MAX_SCAN_BLOCKS 128

__device__ int g_deg[MAX_NDST];
__device__ int g_rowptr[MAX_NDST + 1];
__device__ int g_cursor[MAX_NDST];
__device__ int g_cols[MAX_E];
__device__ int g_blksums[MAX_SCAN_BLOCKS];

// ---------------------------------------------------------------------------
__global__ void k_zero_deg(int n) {
    int i = blockIdx.x * blockDim.x + threadIdx.x;
    if (i < n) g_deg[i] = 0;
}

__global__ void k_count(const int* __restrict__ erow, int E) {
    int e = blockIdx.x * blockDim.x + threadIdx.x;
    if (e < E) atomicAdd(&g_deg[erow[e]], 1);
}

// per-block inclusive scan -> exclusive, record block sums
__global__ void k_scan_partial(int n) {
    __shared__ int sh[SCAN_B];
    int i = blockIdx.x * SCAN_B + threadIdx.x;
    int v = (i < n) ? g_deg[i] : 0;
    sh[threadIdx.x] = v;
    __syncthreads();
#pragma unroll
    for (int off = 1; off < SCAN_B; off <<= 1) {
        int t = (threadIdx.x >= off) ? sh[threadIdx.x - off] : 0;
        __syncthreads();
        sh[threadIdx.x] += t;
        __syncthreads();
    }
    if (i < n) g_rowptr[i] = sh[threadIdx.x] - v;
    if (threadIdx.x == SCAN_B - 1) g_blksums[blockIdx.x] = sh[SCAN_B - 1];
}

// fold block-sum prefix into the add step (removes the serial scan kernel)
__global__ void k_scan_add(int n, int E) {
    __shared__ int wsum[32];
    __shared__ int total;
    int lane = threadIdx.x & 31;
    int wid  = threadIdx.x >> 5;

    int local = 0;
    for (int j = threadIdx.x; j < blockIdx.x; j += blockDim.x)
        local += g_blksums[j];
#pragma unroll
    for (int o = 16; o > 0; o >>= 1) local += __shfl_down_sync(0xffffffffu, local, o);
    if (lane == 0) wsum[wid] = local;
    __syncthreads();
    if (wid == 0) {
        int s = (lane < (int)(blockDim.x >> 5)) ? wsum[lane] : 0;
#pragma unroll
        for (int o = 16; o > 0; o >>= 1) s += __shfl_down_sync(0xffffffffu, s, o);
        if (lane == 0) total = s;
    }
    __syncthreads();

    int i = blockIdx.x * SCAN_B + threadIdx.x;
    if (i < n) {
        int v = g_rowptr[i] + total;
        g_rowptr[i] = v;
        g_cursor[i] = v;
    }
    if (blockIdx.x == 0 && threadIdx.x == 0) g_rowptr[n] = E;
}

__global__ void k_fill(const int* __restrict__ erow, const int* __restrict__ ecol, int E) {
    int e = blockIdx.x * blockDim.x + threadIdx.x;
    if (e < E) {
        int r = erow[e];
        int p = atomicAdd(&g_cursor[r], 1);
        g_cols[p] = ecol[e];
    }
}

// ---------------------------------------------------------------------------
// tf32 tensor-core GEMM: C[M,128] = A[M,256] @ B[256,128]
// All of B lives in smem (stride 136 floats -> conflict-free b-frag loads).
// 512 threads = 16 warps, each warp owns a 16-row strip; BM = 256.
// mma.sync.aligned.m16n8k8.row.col.f32.tf32.tf32.f32
// ---------------------------------------------------------------------------
#define BS_STRIDE 136   // 128 + 8 pad: bank(k*136+n) = (8k+n)%32 -> all distinct
#define GEMM_BM   256

__device__ __forceinline__ uint32_t f2tf32(float x) {
    uint32_t r;
    asm("cvt.rna.tf32.f32 %0, %1;" : "=r"(r) : "f"(x));
    return r;
}

__global__ __launch_bounds__(512, 1)
void k_gemm_tf32(const float* __restrict__ A, const float* __restrict__ B,
                 float* __restrict__ C, int M) {
    extern __shared__ float Bs[];   // [256][BS_STRIDE]

    const int tid = threadIdx.x;

    // ---- stage all of B into smem, rounded to tf32 ----
    // 256 rows x 32 float4 = 8192 float4, 512 threads -> 16 iters
#pragma unroll
    for (int it = 0; it < 16; it++) {
        int idx = tid + it * 512;       // 0..8191
        int r   = idx >> 5;             // 0..255
        int c4  = idx & 31;
        float4 v = *(const float4*)(B + (size_t)r * DD_REL + c4 * 4);
        float* dst = &Bs[r * BS_STRIDE + c4 * 4];
        dst[0] = __uint_as_float(f2tf32(v.x));
        dst[1] = __uint_as_float(f2tf32(v.y));
        dst[2] = __uint_as_float(f2tf32(v.z));
        dst[3] = __uint_as_float(f2tf32(v.w));
    }
    __syncthreads();

    const int warp = tid >> 5;
    const int lane = tid & 31;
    const int gid  = lane >> 2;   // 0..7  (row group / n)
    const int tig  = lane & 3;    // 0..3  (k group)

    const int row0 = blockIdx.x * GEMM_BM + warp * 16;
    const int rA   = row0 + gid;
    const int rA8  = rA + 8;
    const bool okA  = (rA  < M);
    const bool okA8 = (rA8 < M);

    const float* aRow  = A + (size_t)rA  * DD_SRC;
    const float* aRow8 = A + (size_t)rA8 * DD_SRC;

    float c[16][4];
#pragma unroll
    for (int nt = 0; nt < 16; nt++)
#pragma unroll
        for (int j = 0; j < 4; j++) c[nt][j] = 0.f;

#pragma unroll 4
    for (int ks = 0; ks < 32; ks++) {
        const int k0 = ks * 8;
        uint32_t a0 = f2tf32(okA  ? __ldg(aRow  + k0 + tig)     : 0.f);
        uint32_t a1 = f2tf32(okA8 ? __ldg(aRow8 + k0 + tig)     : 0.f);
        uint32_t a2 = f2tf32(okA  ? __ldg(aRow  + k0 + tig + 4) : 0.f);
        uint32_t a3 = f2tf32(okA8 ? __ldg(aRow8 + k0 + tig + 4) : 0.f);

        const float* bk0 = &Bs[(k0 + tig) * BS_STRIDE + gid];
        const float* bk1 = bk0 + 4 * BS_STRIDE;
#pragma unroll
        for (int nt = 0; nt < 16; nt++) {
            uint32_t b0 = __float_as_uint(bk0[nt * 8]);
            uint32_t b1 = __float_as_uint(bk1[nt * 8]);
            asm volatile(
                "mma.sync.aligned.m16n8k8.row.col.f32.tf32.tf32.f32 "
                "{%0,%1,%2,%3}, {%4,%5,%6,%7}, {%8,%9}, {%0,%1,%2,%3};\n"
                : "+f"(c[nt][0]), "+f"(c[nt][1]), "+f"(c[nt][2]), "+f"(c[nt][3])
                : "r"(a0), "r"(a1), "r"(a2), "r"(a3), "r"(b0), "r"(b1));
        }
    }

    // ---- store: c0,c1 -> (rA, 2tig), c2,c3 -> (rA8, 2tig) per n-tile ----
#pragma unroll
    for (int nt = 0; nt < 16; nt++) {
        int col = nt * 8 + 2 * tig;
        if (okA) {
            float2 v = make_float2(c[nt][0], c[nt][1]);
            *(float2*)(C + (size_t)rA * DD_REL + col) = v;
        }
        if (okA8) {
            float2 v = make_float2(c[nt][2], c[nt][3]);
            *(float2*)(C + (size_t)rA8 * DD_REL + col) = v;
        }
    }
}

// ---------------------------------------------------------------------------
// aggregation: one warp per dst row, float4 per lane, 4-way unrolled gather
// ---------------------------------------------------------------------------
__global__ void k_aggregate(const float* __restrict__ src_proj,
                            float* __restrict__ dst_out,
                            float* __restrict__ deg_out,
                            int n_dst) {
    int gwarp = (blockIdx.x * blockDim.x + threadIdx.x) >> 5;
    int lane  = threadIdx.x & 31;
    if (gwarp >= n_dst) return;

    int beg = g_rowptr[gwarp];
    int end = g_rowptr[gwarp + 1];

    const float4* sp = (const float4*)src_proj;   // row stride = 32 float4
    float4 acc = make_float4(0.f, 0.f, 0.f, 0.f);

    int e = beg;
    for (; e + 4 <= end; e += 4) {
        int c0 = g_cols[e];
        int c1 = g_cols[e + 1];
        int c2 = g_cols[e + 2];
        int c3 = g_cols[e + 3];
        float4 v0 = __ldg(&sp[(size_t)c0 * 32 + lane]);
        float4 v1 = __ldg(&sp[(size_t)c1 * 32 + lane]);
        float4 v2 = __ldg(&sp[(size_t)c2 * 32 + lane]);
        float4 v3 = __ldg(&sp[(size_t)c3 * 32 + lane]);
        acc.x += (v0.x + v1.x) + (v2.x + v3.x);
        acc.y += (v0.y + v1.y) + (v2.y + v3.y);
        acc.z += (v0.z + v1.z) + (v2.z + v3.z);
        acc.w += (v0.w + v1.w) + (v2.w + v3.w);
    }
    for (; e < end; e++) {
        int c0 = g_cols[e];
        float4 v0 = __ldg(&sp[(size_t)c0 * 32 + lane]);
        acc.x += v0.x; acc.y += v0.y; acc.z += v0.z; acc.w += v0.w;
    }

    float d = fmaxf((float)(end - beg), 1.f);
    float inv = 1.f / d;
    acc.x *= inv; acc.y *= inv; acc.z *= inv; acc.w *= inv;

    ((float4*)dst_out)[(size_t)gwarp * 32 + lane] = acc;
    if (lane == 0) deg_out[gwarp] = d;
}

// ---------------------------------------------------------------------------
extern "C" void kernel_launch(void* const* d_in, const int* in_sizes, int n_in,
                              void* d_out, int out_size) {
    const float* x_src = (const float*)d_in[0];
    const float* W_src = (const float*)d_in[2];
    const int*   erow  = (const int*)d_in[4];
    const int*   ecol  = (const int*)d_in[5];

    const int N_src = in_sizes[0] / DD_SRC;
    const int N_dst = in_sizes[1] / DD_DST;
    const int E     = in_sizes[4];

    float* out         = (float*)d_out;
    float* dst_out     = out;                                    // [N_dst,128]
    float* srcproj_out = out + (size_t)N_dst * DD_REL;           // [N_src,128]
    float* deg_out     = srcproj_out + (size_t)N_src * DD_REL;   // [N_dst]

    // --- CSR build ---
    k_zero_deg<<<(N_dst + 255) / 256, 256>>>(N_dst);
    k_count<<<(E + 255) / 256, 256>>>(erow, E);
    int nb = (N_dst + SCAN_B - 1) / SCAN_B;
    k_scan_partial<<<nb, SCAN_B>>>(N_dst);
    k_scan_add<<<nb, SCAN_B>>>(N_dst, E);
    k_fill<<<(E + 255) / 256, 256>>>(erow, ecol, E);

    // --- tf32 projection GEMM ---
    static int smem_set = 0;
    const int smem_bytes = 256 * BS_STRIDE * sizeof(float);   // ~139 KB
    if (!smem_set) {
        cudaFuncSetAttribute(k_gemm_tf32,
                             cudaFuncAttributeMaxDynamicSharedMemorySize, smem_bytes);
        smem_set = 1;
    }
    int gm_blocks = (N_src + GEMM_BM - 1) / GEMM_BM;
    k_gemm_tf32<<<gm_blocks, 512, smem_bytes>>>(x_src, W_src, srcproj_out, N_src);

    // --- aggregation ---
    int agg_blocks = (N_dst + 7) / 8;   // 8 warps / 256-thread block
    k_aggregate<<<agg_blocks, 256>>>(srcproj_out, dst_out, deg_out, N_dst);
}

// round 3
// speedup vs baseline: 1.9593x; 1.0530x over previous
#include <cuda_runtime.h>
#include <cuda_bf16.h>
#include <cstdint>

// ---------------------------------------------------------------------------
// RelKDAdapter on GB300:
//   src_proj = x_src @ W_src   (tf32 tensor-core GEMM, M=100000 K=256 N=128)
//   deg      = max(#edges per dst, 1)
//   dst      = segment-mean of src_proj[edge_col] over edge_row  (CSR gather)
// R3: CSR build forked onto a side stream (overlaps GEMM); GEMM retiled to
//     32x64 per warp (B fragments reused across 2 m-tiles -> LDS halved).
// ---------------------------------------------------------------------------

#define DD_SRC   256
#define DD_DST   64
#define DD_REL   128
#define MAX_NDST 100000
#define MAX_E    640000
#define SCAN_B   1024
#define MAX_SCAN_BLOCKS 128

__device__ int g_deg[MAX_NDST];
__device__ int g_rowptr[MAX_NDST + 1];
__device__ int g_cursor[MAX_NDST];
__device__ int g_cols[MAX_E];
__device__ int g_blksums[MAX_SCAN_BLOCKS];

// ---------------------------------------------------------------------------
__global__ void k_zero_deg(int n) {
    int i = blockIdx.x * blockDim.x + threadIdx.x;
    if (i < n) g_deg[i] = 0;
}

__global__ void k_count(const int* __restrict__ erow, int E) {
    int e = blockIdx.x * blockDim.x + threadIdx.x;
    if (e < E) atomicAdd(&g_deg[erow[e]], 1);
}

// per-block inclusive scan -> exclusive, record block sums
__global__ void k_scan_partial(int n) {
    __shared__ int sh[SCAN_B];
    int i = blockIdx.x * SCAN_B + threadIdx.x;
    int v = (i < n) ? g_deg[i] : 0;
    sh[threadIdx.x] = v;
    __syncthreads();
#pragma unroll
    for (int off = 1; off < SCAN_B; off <<= 1) {
        int t = (threadIdx.x >= off) ? sh[threadIdx.x - off] : 0;
        __syncthreads();
        sh[threadIdx.x] += t;
        __syncthreads();
    }
    if (i < n) g_rowptr[i] = sh[threadIdx.x] - v;
    if (threadIdx.x == SCAN_B - 1) g_blksums[blockIdx.x] = sh[SCAN_B - 1];
}

// fold the block-sum prefix into the add step
__global__ void k_scan_add(int n, int E) {
    __shared__ int wsum[32];
    __shared__ int total;
    int lane = threadIdx.x & 31;
    int wid  = threadIdx.x >> 5;

    int local = 0;
    for (int j = threadIdx.x; j < blockIdx.x; j += blockDim.x)
        local += g_blksums[j];
#pragma unroll
    for (int o = 16; o > 0; o >>= 1) local += __shfl_down_sync(0xffffffffu, local, o);
    if (lane == 0) wsum[wid] = local;
    __syncthreads();
    if (wid == 0) {
        int s = (lane < (int)(blockDim.x >> 5)) ? wsum[lane] : 0;
#pragma unroll
        for (int o = 16; o > 0; o >>= 1) s += __shfl_down_sync(0xffffffffu, s, o);
        if (lane == 0) total = s;
    }
    __syncthreads();

    int i = blockIdx.x * SCAN_B + threadIdx.x;
    if (i < n) {
        int v = g_rowptr[i] + total;
        g_rowptr[i] = v;
        g_cursor[i] = v;
    }
    if (blockIdx.x == 0 && threadIdx.x == 0) g_rowptr[n] = E;
}

__global__ void k_fill(const int* __restrict__ erow, const int* __restrict__ ecol, int E) {
    int e = blockIdx.x * blockDim.x + threadIdx.x;
    if (e < E) {
        int r = erow[e];
        int p = atomicAdd(&g_cursor[r], 1);
        g_cols[p] = ecol[e];
    }
}

// ---------------------------------------------------------------------------
// tf32 tensor-core GEMM: C[M,128] = A[M,256] @ B[256,128]
// All of B in smem (stride 136 floats -> conflict-free fragment loads).
// 512 threads = 16 warps; warp tile = 32 rows x 64 cols (2 m-tiles share each
// B fragment). BM = 256.
// ---------------------------------------------------------------------------
#define BS_STRIDE 136   // bank(k*136 + n) = (8k+n)%32 -> all 32 banks distinct
#define GEMM_BM   256

__device__ __forceinline__ uint32_t f2tf32(float x) {
    uint32_t r;
    asm("cvt.rna.tf32.f32 %0, %1;" : "=r"(r) : "f"(x));
    return r;
}

__global__ __launch_bounds__(512, 1)
void k_gemm_tf32(const float* __restrict__ A, const float* __restrict__ B,
                 float* __restrict__ C, int M) {
    extern __shared__ float Bs[];   // [256][BS_STRIDE]

    const int tid = threadIdx.x;

    // ---- stage all of B into smem, rounded to tf32 ----
#pragma unroll
    for (int it = 0; it < 16; it++) {
        int idx = tid + it * 512;       // 0..8191
        int r   = idx >> 5;             // 0..255
        int c4  = idx & 31;
        float4 v = *(const float4*)(B + (size_t)r * DD_REL + c4 * 4);
        float* dst = &Bs[r * BS_STRIDE + c4 * 4];
        dst[0] = __uint_as_float(f2tf32(v.x));
        dst[1] = __uint_as_float(f2tf32(v.y));
        dst[2] = __uint_as_float(f2tf32(v.z));
        dst[3] = __uint_as_float(f2tf32(v.w));
    }
    __syncthreads();

    const int warp = tid >> 5;
    const int lane = tid & 31;
    const int gid  = lane >> 2;   // 0..7
    const int tig  = lane & 3;    // 0..3
    const int wm   = warp >> 1;   // 0..7  -> m strip of 32 rows
    const int wn   = warp & 1;    // 0..1  -> n half of 64 cols

    const int row0 = blockIdx.x * GEMM_BM + wm * 32;
    const int rA = row0 + gid;          // m-tile 0: rows rA, rA+8
    const int rB = row0 + 16 + gid;     // m-tile 1: rows rB, rB+8
    const bool okA  = (rA      < M);
    const bool okA8 = (rA + 8  < M);
    const bool okB  = (rB      < M);
    const bool okB8 = (rB + 8  < M);

    const float* pA  = A + (size_t)rA * DD_SRC;
    const float* pA8 = pA + 8 * DD_SRC;
    const float* pB  = A + (size_t)rB * DD_SRC;
    const float* pB8 = pB + 8 * DD_SRC;

    float c0[8][4], c1[8][4];
#pragma unroll
    for (int nt = 0; nt < 8; nt++)
#pragma unroll
        for (int j = 0; j < 4; j++) { c0[nt][j] = 0.f; c1[nt][j] = 0.f; }

#pragma unroll 4
    for (int ks = 0; ks < 32; ks++) {
        const int k0 = ks * 8;
        uint32_t a00 = f2tf32(okA  ? __ldg(pA  + k0 + tig)     : 0.f);
        uint32_t a01 = f2tf32(okA8 ? __ldg(pA8 + k0 + tig)     : 0.f);
        uint32_t a02 = f2tf32(okA  ? __ldg(pA  + k0 + tig + 4) : 0.f);
        uint32_t a03 = f2tf32(okA8 ? __ldg(pA8 + k0 + tig + 4) : 0.f);
        uint32_t a10 = f2tf32(okB  ? __ldg(pB  + k0 + tig)     : 0.f);
        uint32_t a11 = f2tf32(okB8 ? __ldg(pB8 + k0 + tig)     : 0.f);
        uint32_t a12 = f2tf32(okB  ? __ldg(pB  + k0 + tig + 4) : 0.f);
        uint32_t a13 = f2tf32(okB8 ? __ldg(pB8 + k0 + tig + 4) : 0.f);

        const float* bk0 = &Bs[(k0 + tig) * BS_STRIDE + wn * 64 + gid];
        const float* bk1 = bk0 + 4 * BS_STRIDE;
#pragma unroll
        for (int nt = 0; nt < 8; nt++) {
            uint32_t b0 = __float_as_uint(bk0[nt * 8]);
            uint32_t b1 = __float_as_uint(bk1[nt * 8]);
            asm volatile(
                "mma.sync.aligned.m16n8k8.row.col.f32.tf32.tf32.f32 "
                "{%0,%1,%2,%3}, {%4,%5,%6,%7}, {%8,%9}, {%0,%1,%2,%3};\n"
                : "+f"(c0[nt][0]), "+f"(c0[nt][1]), "+f"(c0[nt][2]), "+f"(c0[nt][3])
                : "r"(a00), "r"(a01), "r"(a02), "r"(a03), "r"(b0), "r"(b1));
            asm volatile(
                "mma.sync.aligned.m16n8k8.row.col.f32.tf32.tf32.f32 "
                "{%0,%1,%2,%3}, {%4,%5,%6,%7}, {%8,%9}, {%0,%1,%2,%3};\n"
                : "+f"(c1[nt][0]), "+f"(c1[nt][1]), "+f"(c1[nt][2]), "+f"(c1[nt][3])
                : "r"(a10), "r"(a11), "r"(a12), "r"(a13), "r"(b0), "r"(b1));
        }
    }

    // ---- store ----
#pragma unroll
    for (int nt = 0; nt < 8; nt++) {
        int col = wn * 64 + nt * 8 + 2 * tig;
        if (okA)  *(float2*)(C + (size_t)rA       * DD_REL + col) = make_float2(c0[nt][0], c0[nt][1]);
        if (okA8) *(float2*)(C + (size_t)(rA + 8) * DD_REL + col) = make_float2(c0[nt][2], c0[nt][3]);
        if (okB)  *(float2*)(C + (size_t)rB       * DD_REL + col) = make_float2(c1[nt][0], c1[nt][1]);
        if (okB8) *(float2*)(C + (size_t)(rB + 8) * DD_REL + col) = make_float2(c1[nt][2], c1[nt][3]);
    }
}

// ---------------------------------------------------------------------------
// aggregation: one warp per dst row, float4 per lane, 4-way unrolled gather
// ---------------------------------------------------------------------------
__global__ void k_aggregate(const float* __restrict__ src_proj,
                            float* __restrict__ dst_out,
                            float* __restrict__ deg_out,
                            int n_dst) {
    int gwarp = (blockIdx.x * blockDim.x + threadIdx.x) >> 5;
    int lane  = threadIdx.x & 31;
    if (gwarp >= n_dst) return;

    int beg = g_rowptr[gwarp];
    int end = g_rowptr[gwarp + 1];

    const float4* sp = (const float4*)src_proj;   // row stride = 32 float4
    float4 acc = make_float4(0.f, 0.f, 0.f, 0.f);

    int e = beg;
    for (; e + 4 <= end; e += 4) {
        int c0 = g_cols[e];
        int c1 = g_cols[e + 1];
        int c2 = g_cols[e + 2];
        int c3 = g_cols[e + 3];
        float4 v0 = __ldg(&sp[(size_t)c0 * 32 + lane]);
        float4 v1 = __ldg(&sp[(size_t)c1 * 32 + lane]);
        float4 v2 = __ldg(&sp[(size_t)c2 * 32 + lane]);
        float4 v3 = __ldg(&sp[(size_t)c3 * 32 + lane]);
        acc.x += (v0.x + v1.x) + (v2.x + v3.x);
        acc.y += (v0.y + v1.y) + (v2.y + v3.y);
        acc.z += (v0.z + v1.z) + (v2.z + v3.z);
        acc.w += (v0.w + v1.w) + (v2.w + v3.w);
    }
    for (; e < end; e++) {
        int c0 = g_cols[e];
        float4 v0 = __ldg(&sp[(size_t)c0 * 32 + lane]);
        acc.x += v0.x; acc.y += v0.y; acc.z += v0.z; acc.w += v0.w;
    }

    float d = fmaxf((float)(end - beg), 1.f);
    float inv = 1.f / d;
    acc.x *= inv; acc.y *= inv; acc.z *= inv; acc.w *= inv;

    ((float4*)dst_out)[(size_t)gwarp * 32 + lane] = acc;
    if (lane == 0) deg_out[gwarp] = d;
}

// ---------------------------------------------------------------------------
extern "C" void kernel_launch(void* const* d_in, const int* in_sizes, int n_in,
                              void* d_out, int out_size) {
    const float* x_src = (const float*)d_in[0];
    const float* W_src = (const float*)d_in[2];
    const int*   erow  = (const int*)d_in[4];
    const int*   ecol  = (const int*)d_in[5];

    const int N_src = in_sizes[0] / DD_SRC;
    const int N_dst = in_sizes[1] / DD_DST;
    const int E     = in_sizes[4];

    float* out         = (float*)d_out;
    float* dst_out     = out;                                    // [N_dst,128]
    float* srcproj_out = out + (size_t)N_dst * DD_REL;           // [N_src,128]
    float* deg_out     = srcproj_out + (size_t)N_src * DD_REL;   // [N_dst]

    // One-time setup (first call is outside graph capture).
    static cudaStream_t s_csr = nullptr;
    static cudaEvent_t  ev_fork = nullptr, ev_join = nullptr;
    static int smem_set = 0;
    const int smem_bytes = 256 * BS_STRIDE * sizeof(float);   // ~139 KB
    if (!smem_set) {
        cudaFuncSetAttribute(k_gemm_tf32,
                             cudaFuncAttributeMaxDynamicSharedMemorySize, smem_bytes);
        cudaStreamCreateWithFlags(&s_csr, cudaStreamNonBlocking);
        cudaEventCreateWithFlags(&ev_fork, cudaEventDisableTiming);
        cudaEventCreateWithFlags(&ev_join, cudaEventDisableTiming);
        smem_set = 1;
    }

    // Fork: CSR build runs on s_csr, concurrent with the GEMM on stream 0.
    cudaEventRecord(ev_fork, 0);
    cudaStreamWaitEvent(s_csr, ev_fork, 0);

    // --- CSR branch (side stream) ---
    k_zero_deg<<<(N_dst + 255) / 256, 256, 0, s_csr>>>(N_dst);
    k_count<<<(E + 255) / 256, 256, 0, s_csr>>>(erow, E);
    int nb = (N_dst + SCAN_B - 1) / SCAN_B;
    k_scan_partial<<<nb, SCAN_B, 0, s_csr>>>(N_dst);
    k_scan_add<<<nb, SCAN_B, 0, s_csr>>>(N_dst, E);
    k_fill<<<(E + 255) / 256, 256, 0, s_csr>>>(erow, ecol, E);
    cudaEventRecord(ev_join, s_csr);

    // --- tf32 projection GEMM (main stream, overlapped with CSR) ---
    int gm_blocks = (N_src + GEMM_BM - 1) / GEMM_BM;
    k_gemm_tf32<<<gm_blocks, 512, smem_bytes>>>(x_src, W_src, srcproj_out, N_src);

    // Join: aggregation needs both the CSR and src_proj.
    cudaStreamWaitEvent(0, ev_join, 0);

    // --- aggregation ---
    int agg_blocks = (N_dst + 7) / 8;   // 8 warps / 256-thread block
    k_aggregate<<<agg_blocks, 256>>>(srcproj_out, dst_out, deg_out, N_dst);
}

// round 5
// speedup vs baseline: 2.5694x; 1.3114x over previous
#include <cuda_runtime.h>
#include <cuda_fp16.h>
#include <cuda_bf16.h>
#include <cstdint>

// ---------------------------------------------------------------------------
// RelKDAdapter on GB300 (sm_103 legacy-PTX target -> no tcgen05):
//   src_proj = x_src @ W_src   (fp16-input tensor-core GEMM, fp32 accum;
//                               fp16 mantissa == tf32 mantissa -> same error)
//   deg      = max(#edges per dst, 1)
//   dst      = segment-mean of src_proj[edge_col] over edge_row  (CSR gather)
// R5: mma.sync m16n8k16.f16 halves HMMA count vs tf32 m16n8k8.
// ---------------------------------------------------------------------------

#define DD_SRC   256
#define DD_DST   64
#define DD_REL   128
#define MAX_NDST 100000
#define MAX_E    640000
#define SCAN_B   1024
#define MAX_SCAN_BLOCKS 128

__device__ int g_deg[MAX_NDST];
__device__ int g_rowptr[MAX_NDST + 1];
__device__ int g_cursor[MAX_NDST];
__device__ int g_cols[MAX_E];
__device__ int g_blksums[MAX_SCAN_BLOCKS];
__device__ __half g_Bh[DD_REL * DD_SRC];   // W_src transposed: [128 n][256 k], fp16

// ===========================================================================
// CSR build
// ===========================================================================
__global__ void k_zero_deg(int n) {
    int i = blockIdx.x * blockDim.x + threadIdx.x;
    if (i < n) g_deg[i] = 0;
}
__global__ void k_count(const int* __restrict__ erow, int E) {
    int e = blockIdx.x * blockDim.x + threadIdx.x;
    if (e < E) atomicAdd(&g_deg[erow[e]], 1);
}
__global__ void k_scan_partial(int n) {
    __shared__ int sh[SCAN_B];
    int i = blockIdx.x * SCAN_B + threadIdx.x;
    int v = (i < n) ? g_deg[i] : 0;
    sh[threadIdx.x] = v;
    __syncthreads();
#pragma unroll
    for (int off = 1; off < SCAN_B; off <<= 1) {
        int t = (threadIdx.x >= off) ? sh[threadIdx.x - off] : 0;
        __syncthreads();
        sh[threadIdx.x] += t;
        __syncthreads();
    }
    if (i < n) g_rowptr[i] = sh[threadIdx.x] - v;
    if (threadIdx.x == SCAN_B - 1) g_blksums[blockIdx.x] = sh[SCAN_B - 1];
}
__global__ void k_scan_add(int n, int E) {
    __shared__ int wsum[32];
    __shared__ int total;
    int lane = threadIdx.x & 31, wid = threadIdx.x >> 5;
    int local = 0;
    for (int j = threadIdx.x; j < blockIdx.x; j += blockDim.x) local += g_blksums[j];
#pragma unroll
    for (int o = 16; o > 0; o >>= 1) local += __shfl_down_sync(0xffffffffu, local, o);
    if (lane == 0) wsum[wid] = local;
    __syncthreads();
    if (wid == 0) {
        int s = (lane < (int)(blockDim.x >> 5)) ? wsum[lane] : 0;
#pragma unroll
        for (int o = 16; o > 0; o >>= 1) s += __shfl_down_sync(0xffffffffu, s, o);
        if (lane == 0) total = s;
    }
    __syncthreads();
    int i = blockIdx.x * SCAN_B + threadIdx.x;
    if (i < n) {
        int v = g_rowptr[i] + total;
        g_rowptr[i] = v;
        g_cursor[i] = v;
    }
    if (blockIdx.x == 0 && threadIdx.x == 0) g_rowptr[n] = E;
}
__global__ void k_fill(const int* __restrict__ erow, const int* __restrict__ ecol, int E) {
    int e = blockIdx.x * blockDim.x + threadIdx.x;
    if (e < E) {
        int r = erow[e];
        int p = atomicAdd(&g_cursor[r], 1);
        g_cols[p] = ecol[e];
    }
}

// ===========================================================================
// B transpose + fp16 convert: g_Bh[n][k] = half(W[k][n]);  W is [256][128]
// ===========================================================================
__global__ void k_transB(const float* __restrict__ W) {
    int i = blockIdx.x * 256 + threadIdx.x;
    if (i < DD_REL * DD_SRC) {
        int n = i >> 8;        // 0..127
        int k = i & 255;       // 0..255
        g_Bh[i] = __float2half_rn(W[k * DD_REL + n]);
    }
}

// ===========================================================================
// fp16 tensor-core GEMM: C[M,128] = A[M,256] @ Bh^T, fp32 accumulate.
// All of Bh in smem: 128 rows x 528B (256 halfs + 8 pad) = 67584B.
//   b-frag LDS bank = (4*gid + tig) % 32 -> conflict-free.
// 512 threads = 16 warps; warp tile = 32 rows x 64 cols; BM = 256.
// mma.sync.aligned.m16n8k16.row.col.f32.f16.f16.f32 (2048 MACs/instr).
// ===========================================================================
#define GEMM_BM 256
#define BROW    528          // bytes per B smem row
#define SMEM_SZ (128 * BROW) // 67584

__device__ __forceinline__ uint32_t pack_h2(float x, float y) {
    __half2 h = __floats2half2_rn(x, y);
    return *(uint32_t*)&h;
}

__global__ __launch_bounds__(512, 1)
void k_gemm_f16(const float* __restrict__ A, float* __restrict__ C, int M) {
    extern __shared__ char smemc[];
    const int tid = threadIdx.x;

    // ---- stage Bh into smem via cp.async (16B chunks, padded rows) ----
    {
        const char* src_base = (const char*)g_Bh;
#pragma unroll
        for (int t = 0; t < 8; t++) {
            int i = tid + t * 512;      // 0..4095
            int n = i >> 5;             // 0..127
            int q = i & 31;             // 16B chunk (32 per 512B row)
            uint32_t dst;
            asm("{ .reg .u64 tt; cvta.to.shared.u64 tt, %1; cvt.u32.u64 %0, tt; }"
                : "=r"(dst) : "l"(smemc + n * BROW + q * 16));
            const char* src = src_base + (size_t)n * 512 + q * 16;
            asm volatile("cp.async.cg.shared.global [%0], [%1], 16;" :: "r"(dst), "l"(src));
        }
        asm volatile("cp.async.commit_group;" ::: "memory");
        asm volatile("cp.async.wait_group 0;" ::: "memory");
    }
    __syncthreads();

    const int warp = tid >> 5;
    const int lane = tid & 31;
    const int gid  = lane >> 2;   // 0..7
    const int tig  = lane & 3;    // 0..3
    const int wm   = warp >> 1;   // 0..7 -> 32-row strip
    const int wn   = warp & 1;    // 0..1 -> 64-col half

    const int row0 = blockIdx.x * GEMM_BM + wm * 32;
    const int rA = row0 + gid;        // m-tile 0 rows: rA, rA+8
    const int rB = row0 + 16 + gid;   // m-tile 1 rows: rB, rB+8
    const bool okA  = (rA      < M);
    const bool okA8 = (rA + 8  < M);
    const bool okB  = (rB      < M);
    const bool okB8 = (rB + 8  < M);

    // clamp row pointers for safe (discarded) OOB loads
    const int cl = M - 1;
    const float* pA0 = A + (size_t)(okA  ? rA     : cl) * DD_SRC;
    const float* pA1 = A + (size_t)(okA8 ? rA + 8 : cl) * DD_SRC;
    const float* pB0 = A + (size_t)(okB  ? rB     : cl) * DD_SRC;
    const float* pB1 = A + (size_t)(okB8 ? rB + 8 : cl) * DD_SRC;

    // per-lane B base: row n = wn*64 + nt*8 + gid, byte off (2*tig)*2
    const char* bbase = smemc + (wn * 64 + gid) * BROW + tig * 4;

    float c0[8][4], c1[8][4];
#pragma unroll
    for (int nt = 0; nt < 8; nt++)
#pragma unroll
        for (int j = 0; j < 4; j++) { c0[nt][j] = 0.f; c1[nt][j] = 0.f; }

#pragma unroll 2
    for (int ks = 0; ks < 16; ks++) {
        const int k0 = ks * 16;
        const int kk = k0 + 2 * tig;

        float2 vA0  = __ldg((const float2*)(pA0 + kk));
        float2 vA0b = __ldg((const float2*)(pA0 + kk + 8));
        float2 vA1  = __ldg((const float2*)(pA1 + kk));
        float2 vA1b = __ldg((const float2*)(pA1 + kk + 8));
        float2 vB0  = __ldg((const float2*)(pB0 + kk));
        float2 vB0b = __ldg((const float2*)(pB0 + kk + 8));
        float2 vB1  = __ldg((const float2*)(pB1 + kk));
        float2 vB1b = __ldg((const float2*)(pB1 + kk + 8));

        uint32_t a00 = pack_h2(vA0.x,  vA0.y);    // A[rA][kk,kk+1]
        uint32_t a01 = pack_h2(vA1.x,  vA1.y);    // A[rA+8]
        uint32_t a02 = pack_h2(vA0b.x, vA0b.y);   // A[rA][kk+8,kk+9]
        uint32_t a03 = pack_h2(vA1b.x, vA1b.y);
        uint32_t a10 = pack_h2(vB0.x,  vB0.y);
        uint32_t a11 = pack_h2(vB1.x,  vB1.y);
        uint32_t a12 = pack_h2(vB0b.x, vB0b.y);
        uint32_t a13 = pack_h2(vB1b.x, vB1b.y);

        const char* bk = bbase + k0 * 2;
#pragma unroll
        for (int nt = 0; nt < 8; nt++) {
            uint32_t b0 = *(const uint32_t*)(bk + nt * (8 * BROW));
            uint32_t b1 = *(const uint32_t*)(bk + nt * (8 * BROW) + 16);
            asm volatile(
                "mma.sync.aligned.m16n8k16.row.col.f32.f16.f16.f32 "
                "{%0,%1,%2,%3}, {%4,%5,%6,%7}, {%8,%9}, {%0,%1,%2,%3};\n"
                : "+f"(c0[nt][0]), "+f"(c0[nt][1]), "+f"(c0[nt][2]), "+f"(c0[nt][3])
                : "r"(a00), "r"(a01), "r"(a02), "r"(a03), "r"(b0), "r"(b1));
            asm volatile(
                "mma.sync.aligned.m16n8k16.row.col.f32.f16.f16.f32 "
                "{%0,%1,%2,%3}, {%4,%5,%6,%7}, {%8,%9}, {%0,%1,%2,%3};\n"
                : "+f"(c1[nt][0]), "+f"(c1[nt][1]), "+f"(c1[nt][2]), "+f"(c1[nt][3])
                : "r"(a10), "r"(a11), "r"(a12), "r"(a13), "r"(b0), "r"(b1));
        }
    }

    // ---- store: c[0],c[1] -> row rX col 2tig ; c[2],c[3] -> row rX+8 ----
#pragma unroll
    for (int nt = 0; nt < 8; nt++) {
        int col = wn * 64 + nt * 8 + 2 * tig;
        if (okA)  *(float2*)(C + (size_t)rA       * DD_REL + col) = make_float2(c0[nt][0], c0[nt][1]);
        if (okA8) *(float2*)(C + (size_t)(rA + 8) * DD_REL + col) = make_float2(c0[nt][2], c0[nt][3]);
        if (okB)  *(float2*)(C + (size_t)rB       * DD_REL + col) = make_float2(c1[nt][0], c1[nt][1]);
        if (okB8) *(float2*)(C + (size_t)(rB + 8) * DD_REL + col) = make_float2(c1[nt][2], c1[nt][3]);
    }
}

// ===========================================================================
// aggregation: one warp per dst row, float4 per lane, 4-way unrolled gather
// ===========================================================================
__global__ void k_aggregate(const float* __restrict__ src_proj,
                            float* __restrict__ dst_out,
                            float* __restrict__ deg_out,
                            int n_dst) {
    int gwarp = (blockIdx.x * blockDim.x + threadIdx.x) >> 5;
    int lane  = threadIdx.x & 31;
    if (gwarp >= n_dst) return;

    int beg = g_rowptr[gwarp];
    int end = g_rowptr[gwarp + 1];

    const float4* sp = (const float4*)src_proj;
    float4 acc = make_float4(0.f, 0.f, 0.f, 0.f);

    int e = beg;
    for (; e + 4 <= end; e += 4) {
        int c0 = g_cols[e], c1 = g_cols[e + 1], c2 = g_cols[e + 2], c3 = g_cols[e + 3];
        float4 v0 = __ldg(&sp[(size_t)c0 * 32 + lane]);
        float4 v1 = __ldg(&sp[(size_t)c1 * 32 + lane]);
        float4 v2 = __ldg(&sp[(size_t)c2 * 32 + lane]);
        float4 v3 = __ldg(&sp[(size_t)c3 * 32 + lane]);
        acc.x += (v0.x + v1.x) + (v2.x + v3.x);
        acc.y += (v0.y + v1.y) + (v2.y + v3.y);
        acc.z += (v0.z + v1.z) + (v2.z + v3.z);
        acc.w += (v0.w + v1.w) + (v2.w + v3.w);
    }
    for (; e < end; e++) {
        int c0 = g_cols[e];
        float4 v0 = __ldg(&sp[(size_t)c0 * 32 + lane]);
        acc.x += v0.x; acc.y += v0.y; acc.z += v0.z; acc.w += v0.w;
    }

    float d = fmaxf((float)(end - beg), 1.f);
    float inv = 1.f / d;
    acc.x *= inv; acc.y *= inv; acc.z *= inv; acc.w *= inv;

    ((float4*)dst_out)[(size_t)gwarp * 32 + lane] = acc;
    if (lane == 0) deg_out[gwarp] = d;
}

// ===========================================================================
extern "C" void kernel_launch(void* const* d_in, const int* in_sizes, int n_in,
                              void* d_out, int out_size) {
    const float* x_src = (const float*)d_in[0];
    const float* W_src = (const float*)d_in[2];
    const int*   erow  = (const int*)d_in[4];
    const int*   ecol  = (const int*)d_in[5];

    const int N_src = in_sizes[0] / DD_SRC;
    const int N_dst = in_sizes[1] / DD_DST;
    const int E     = in_sizes[4];

    float* out         = (float*)d_out;
    float* dst_out     = out;
    float* srcproj_out = out + (size_t)N_dst * DD_REL;
    float* deg_out     = srcproj_out + (size_t)N_src * DD_REL;

    static cudaStream_t s_csr = nullptr;
    static cudaEvent_t  ev_fork = nullptr, ev_join = nullptr;
    static int init_done = 0;
    if (!init_done) {
        cudaFuncSetAttribute(k_gemm_f16,
                             cudaFuncAttributeMaxDynamicSharedMemorySize, SMEM_SZ);
        cudaStreamCreateWithFlags(&s_csr, cudaStreamNonBlocking);
        cudaEventCreateWithFlags(&ev_fork, cudaEventDisableTiming);
        cudaEventCreateWithFlags(&ev_join, cudaEventDisableTiming);
        init_done = 1;
    }

    cudaEventRecord(ev_fork, 0);
    cudaStreamWaitEvent(s_csr, ev_fork, 0);

    // --- CSR branch (side stream, overlaps transB + GEMM) ---
    k_zero_deg<<<(N_dst + 255) / 256, 256, 0, s_csr>>>(N_dst);
    k_count<<<(E + 255) / 256, 256, 0, s_csr>>>(erow, E);
    int nb = (N_dst + SCAN_B - 1) / SCAN_B;
    k_scan_partial<<<nb, SCAN_B, 0, s_csr>>>(N_dst);
    k_scan_add<<<nb, SCAN_B, 0, s_csr>>>(N_dst, E);
    k_fill<<<(E + 255) / 256, 256, 0, s_csr>>>(erow, ecol, E);
    cudaEventRecord(ev_join, s_csr);

    // --- main stream: B transpose->fp16, then GEMM ---
    k_transB<<<(DD_REL * DD_SRC + 255) / 256, 256>>>(W_src);
    int gm_blocks = (N_src + GEMM_BM - 1) / GEMM_BM;
    k_gemm_f16<<<gm_blocks, 512, SMEM_SZ>>>(x_src, srcproj_out, N_src);

    cudaStreamWaitEvent(0, ev_join, 0);

    // --- aggregation ---
    int agg_blocks = (N_dst + 7) / 8;
    k_aggregate<<<agg_blocks, 256>>>(srcproj_out, dst_out, deg_out, N_dst);
}